// round 16
// baseline (speedup 1.0000x reference)
#include <cuda_runtime.h>
#include <math.h>
#include <stdint.h>

// Shapes: B=32 S=128 N=64 FD=64 H=4 L=32 BASE=4096; out [32,128,4096] f32
#define PAD 68

// ---------------- tf32 rounding ----------------
__device__ __forceinline__ float tf32r(float x) {
    unsigned r;
    asm("cvt.rna.tf32.f32 %0, %1;" : "=r"(r) : "f"(x));
    return __uint_as_float(r);
}

// ---------------- mma.sync m16n8k8 tf32 (fp32 accum) ----------------
__device__ __forceinline__ void mma_tf32(float& d0, float& d1, float& d2, float& d3,
                                         unsigned a0, unsigned a1, unsigned a2, unsigned a3,
                                         unsigned b0, unsigned b1) {
    asm("mma.sync.aligned.m16n8k8.row.col.f32.tf32.tf32.f32 "
        "{%0,%1,%2,%3}, {%4,%5,%6,%7}, {%8,%9}, {%0,%1,%2,%3};"
        : "+f"(d0), "+f"(d1), "+f"(d2), "+f"(d3)
        : "r"(a0), "r"(a1), "r"(a2), "r"(a3), "r"(b0), "r"(b1));
}

// ---------------- device scratch ----------------
__device__ float g_hmid [32 * 8192];
__device__ float g_delta[32 * 2048];
__device__ float g_posemb[64 * 32];
__device__ float g_geom  [64 * 64];
__device__ float g_w     [32 * 64 * 64];
// fragment-order packed weights (tf32-rounded):
// [h][half][kk8][nn][lane] -> float2{b0,b1}
__device__ float2 g_Wq2[8192];
__device__ float2 g_Wk2[8192];
__device__ float2 g_Wv2[8192];
__device__ float2 g_Ws2[2048];

// ---------------- init ----------------
__global__ void k_init(const float* __restrict__ b1, const float* __restrict__ b2) {
    int i = blockIdx.x * 256 + threadIdx.x;
    if (i < 32 * 8192) g_hmid[i] = b1[i & 8191];
    if (i < 32 * 2048) g_delta[i] = b2[i & 2047];
}

__global__ void k_packT(const float* __restrict__ Wq, const float* __restrict__ Wk,
                        const float* __restrict__ Wv, const float* __restrict__ Wskip) {
    int i = blockIdx.x * 256 + threadIdx.x;
    if (i < 8192) {
        int lane = i & 31;
        int nn   = (i >> 5) & 3;
        int kk8  = (i >> 7) & 7;
        int half = (i >> 10) & 1;
        int h    = (i >> 11) & 3;
        int g2 = lane >> 2, t = lane & 3;
        int n = h * 64 + half * 32 + nn * 8 + g2;
        int r0 = kk8 * 8 + t, r1 = r0 + 4;
        g_Wq2[i] = make_float2(tf32r(Wq[r0 * 256 + n]), tf32r(Wq[r1 * 256 + n]));
        g_Wk2[i] = make_float2(tf32r(Wk[r0 * 256 + n]), tf32r(Wk[r1 * 256 + n]));
        g_Wv2[i] = make_float2(tf32r(Wv[r0 * 256 + n]), tf32r(Wv[r1 * 256 + n]));
    }
    if (i < 2048) {
        int lane = i & 31;
        int nn   = (i >> 5) & 3;
        int kk8  = (i >> 7) & 7;
        int half = (i >> 10) & 1;
        int g2 = lane >> 2, t = lane & 3;
        int n = half * 32 + nn * 8 + g2;
        int r0 = kk8 * 8 + t, r1 = r0 + 4;
        g_Ws2[i] = make_float2(tf32r(Wskip[r0 * 64 + n]), tf32r(Wskip[r1 * 64 + n]));
    }
}

// ---------------- MLP layer 1: split-K 64 (fp32 exact, unchanged) ----------------
__global__ void k_mlp1(const float* __restrict__ pooled, const float* __restrict__ W1) {
    __shared__ float sh[64 * 32];
    int tid = threadIdx.x;
    int k0 = blockIdx.y * 64;
    for (int e = tid; e < 2048; e += 256) {
        int b = e & 31, k = e >> 5;
        sh[k * 32 + b] = pooled[b * 4096 + k0 + k];
    }
    __syncthreads();
    int col = blockIdx.x * 256 + tid;
    float acc[32];
#pragma unroll
    for (int b = 0; b < 32; b++) acc[b] = 0.f;
    for (int k = 0; k < 64; k++) {
        float wv = W1[(size_t)(k0 + k) * 8192 + col];
        const float4* sp = (const float4*)&sh[k * 32];
#pragma unroll
        for (int w = 0; w < 8; w++) {
            float4 p = sp[w];
            acc[4 * w + 0] += p.x * wv;
            acc[4 * w + 1] += p.y * wv;
            acc[4 * w + 2] += p.z * wv;
            acc[4 * w + 3] += p.w * wv;
        }
    }
#pragma unroll
    for (int b = 0; b < 32; b++) atomicAdd(&g_hmid[b * 8192 + col], acc[b]);
}

__device__ __forceinline__ float gelu_exact(float x) {
    return 0.5f * x * (1.f + erff(x * 0.70710678118654752f));
}

__global__ void k_mlp2(const float* __restrict__ W2) {
    __shared__ float sh[64 * 32];
    int tid = threadIdx.x;
    int k0 = blockIdx.y * 64;
    for (int e = tid; e < 2048; e += 256) {
        int b = e & 31, k = e >> 5;
        sh[k * 32 + b] = gelu_exact(g_hmid[b * 8192 + k0 + k]);
    }
    __syncthreads();
    int col = blockIdx.x * 256 + tid;
    float acc[32];
#pragma unroll
    for (int b = 0; b < 32; b++) acc[b] = 0.f;
    for (int k = 0; k < 64; k++) {
        float wv = W2[(size_t)(k0 + k) * 2048 + col];
        const float4* sp = (const float4*)&sh[k * 32];
#pragma unroll
        for (int w = 0; w < 8; w++) {
            float4 p = sp[w];
            acc[4 * w + 0] += p.x * wv;
            acc[4 * w + 1] += p.y * wv;
            acc[4 * w + 2] += p.z * wv;
            acc[4 * w + 3] += p.w * wv;
        }
    }
#pragma unroll
    for (int b = 0; b < 32; b++) atomicAdd(&g_delta[b * 2048 + col], acc[b]);
}

// ---------------- setup (bit-exact, unchanged) ----------------
__global__ void k_setup(const float* __restrict__ pos, const float* __restrict__ Wpos) {
    __shared__ float pn[64 * 3];
    __shared__ float emb[64 * 32];
    __shared__ float sqn[64];
    __shared__ float mean[3];
    int tid = threadIdx.x;
    if (tid < 3) {
        float s = 0.f;
        for (int n = 0; n < 64; n++) s += pos[n * 3 + tid];
        mean[tid] = s * (1.f / 64.f);
    }
    __syncthreads();
    if (tid < 64) {
        float c0 = pos[tid * 3 + 0] - mean[0];
        float c1 = pos[tid * 3 + 1] - mean[1];
        float c2 = pos[tid * 3 + 2] - mean[2];
        float nr = sqrtf(c0 * c0 + c1 * c1 + c2 * c2);
        nr = fmaxf(nr, 1e-12f);
        pn[tid * 3 + 0] = c0 / nr;
        pn[tid * 3 + 1] = c1 / nr;
        pn[tid * 3 + 2] = c2 / nr;
    }
    __syncthreads();
    if (tid < 64) {
        float s2 = 0.f;
        for (int l = 0; l < 32; l++) {
            float e = pn[tid * 3 + 0] * Wpos[l]
                    + pn[tid * 3 + 1] * Wpos[32 + l]
                    + pn[tid * 3 + 2] * Wpos[64 + l];
            emb[tid * 32 + l] = e;
            g_posemb[tid * 32 + l] = e;
            s2 += e * e;
        }
        sqn[tid] = s2;
    }
    __syncthreads();
    if (tid < 64) {
        for (int j = 0; j < 64; j++) {
            float dt = 0.f;
            for (int l = 0; l < 32; l++) dt += emb[tid * 32 + l] * emb[j * 32 + l];
            float sq = sqn[tid] + sqn[j] - 2.f * dt;
            g_geom[tid * 64 + j] = (sq > 0.f) ? sqrtf(sq) : 0.f;
        }
    }
}

// ---------------- JAX threefry2x32, partitionable, key(42) ----------------
__device__ __forceinline__ float jax_uniform(unsigned int t) {
    const unsigned int K0 = 0u, K1 = 42u;
    const unsigned int K2 = 0x1BD11BDAu ^ K0 ^ K1;
    unsigned int x0 = 0u + K0;
    unsigned int x1 = t + K1;
    const int rot[8] = {13, 15, 26, 6, 17, 29, 16, 24};
    const unsigned int ks[3] = {K0, K1, K2};
#pragma unroll
    for (int i = 0; i < 5; i++) {
#pragma unroll
        for (int r = 0; r < 4; r++) {
            int rr = rot[(i & 1) * 4 + r];
            x0 += x1;
            x1 = (x1 << rr) | (x1 >> (32 - rr));
            x1 ^= x0;
        }
        x0 += ks[(i + 1) % 3];
        x1 += ks[(i + 2) % 3] + (unsigned)(i + 1);
    }
    unsigned int bits = x0 ^ x1;
    return __uint_as_float((bits >> 9) | 0x3F800000u) - 1.0f;
}

// ---------------- adjacency (bit-exact, unchanged) ----------------
__global__ void k_adj(const float* __restrict__ log_tau, const float* __restrict__ logit_theta,
                      const float* __restrict__ logit_alpha, const float* __restrict__ raw_beta) {
    extern __shared__ float sm[];
    float* z    = sm;
    float* zn   = z + 64 * 33;
    float* dinv = zn + 64;
    float* sc   = dinv + 64;
    float* soft = sc + 64 * 65;
    float* hard = soft + 64 * 65;
    int tid = threadIdx.x;
    int b = blockIdx.x;

    for (int e = tid; e < 2048; e += 256) {
        int n = e >> 5, l = e & 31;
        z[n * 33 + l] = g_posemb[e] + g_delta[b * 2048 + e];
    }
    __syncthreads();
    if (tid < 64) {
        float s = 0.f;
        for (int l = 0; l < 32; l++) { float v = z[tid * 33 + l]; s += v * v; }
        zn[tid] = s;
    }
    __syncthreads();

    float tau   = fmaxf(expf(log_tau[0]), 0.01f);
    float theta = 1.f / (1.f + expf(-logit_theta[0]));
    float alpha = (1.f / (1.f + expf(-logit_alpha[0]))) * 10.f;
    float beta  = fabsf(raw_beta[0]);
    float taue  = tau + 1e-6f;

    for (int p = 0; p < 16; p++) {
        int idx = p * 256 + tid;
        int i = idx >> 6, j = idx & 63;
        float dt = 0.f;
        for (int l = 0; l < 32; l++) dt += z[i * 33 + l] * z[j * 33 + l];
        float sq = zn[i] + zn[j] - 2.f * dt;
        float ld = (sq > 0.f) ? sqrtf(sq) : 0.f;
        float logit = -(ld + beta * g_geom[i * 64 + j]);
        float u = jax_uniform((unsigned)(b * 4096 + idx));
        float gum = -logf(-logf(u + 1e-6f) + 1e-6f);
        sc[i * 65 + j] = (logit + gum) / taue;
    }
    __syncthreads();
    if (tid < 64) {
        float mx = -3e38f;
        for (int j = 0; j < 64; j++) mx = fmaxf(mx, sc[tid * 65 + j]);
        float s = 0.f;
        for (int j = 0; j < 64; j++) {
            float e = expf(sc[tid * 65 + j] - mx);
            soft[tid * 65 + j] = e;
            s += e;
        }
        for (int j = 0; j < 64; j++) soft[tid * 65 + j] = soft[tid * 65 + j] / s;
    }
    __syncthreads();
    for (int p = 0; p < 16; p++) {
        int idx = p * 256 + tid;
        int i = idx >> 6, j = idx & 63;
        float g = 1.f / (1.f + expf(-alpha * (soft[i * 65 + j] - theta)));
        hard[i * 65 + j] = (g > 0.5f) ? 1.f : 0.f;
    }
    __syncthreads();
    for (int p = 0; p < 16; p++) {
        int idx = p * 256 + tid;
        int i = idx >> 6, j = idx & 63;
        float val = (i == j) ? soft[i * 65 + i]
                             : 0.5f * (hard[i * 65 + j] + hard[j * 65 + i]);
        sc[i * 65 + j] = val;
    }
    __syncthreads();
    if (tid < 64) {
        float ds = 0.f;
        for (int j = 0; j < 64; j++) ds += sc[tid * 65 + j];
        dinv[tid] = 1.f / sqrtf(fmaxf(ds, 1e-6f));
    }
    __syncthreads();
    for (int p = 0; p < 16; p++) {
        int idx = p * 256 + tid;
        int i = idx >> 6, j = idx & 63;
        g_w[b * 4096 + idx] = dinv[i] * sc[i * 65 + j] * dinv[j];
    }
}

// ---------------- attention: TF32 mma, 3 CTAs/SM (aliased vtb, split phases) ----
__global__ __launch_bounds__(256, 3) void k_attn(
    const float* __restrict__ nf_all,
    const float* __restrict__ bq, const float* __restrict__ bk,
    const float* __restrict__ bv, const float* __restrict__ We,
    const float* __restrict__ bskip,
    const float* __restrict__ g1, const float* __restrict__ be1,
    const float* __restrict__ g2, const float* __restrict__ be2,
    float* __restrict__ out)
{
    extern __shared__ float sm[];
    float* xn   = sm;                  // [64][PAD] LN(x) tf32
    float* qb   = xn   + 64 * PAD;     // [64][PAD] q (phase A/B); vtb alias (phase C/D)
    float* kb   = qb   + 64 * PAD;     // [64][PAD] k
    float* attb = kb   + 64 * PAD;     // scores -> attn -> result
    float* auxp = attb + 64 * PAD;     // 128: qe partials
    float* aux  = auxp + 128;          // 64: coef
    float* red  = aux  + 64;           // 256
    float* vtb  = qb;                  // ALIAS: v transposed lives in qb region

    int tid = threadIdx.x;
    int bs = blockIdx.x;
    int b = bs >> 7;
    const float* nf = nf_all + (size_t)bs * 4096;
    const float* gw = g_w + b * 4096;

    for (int e = tid; e < 4096; e += 256) {
        xn[(e >> 6) * PAD + (e & 63)] = nf[e];
    }
    __syncthreads();

    int r4 = tid >> 2, q4 = tid & 3;
    // ---- LN1 (quad-parallel), store tf32-rounded ----
    {
        float* xr = &xn[r4 * PAD + q4 * 16];
        float s = 0.f;
#pragma unroll
        for (int c = 0; c < 16; c++) s += xr[c];
        s += __shfl_xor_sync(0xffffffffu, s, 1);
        s += __shfl_xor_sync(0xffffffffu, s, 2);
        float m = s * (1.f / 64.f);
        float v = 0.f;
#pragma unroll
        for (int c = 0; c < 16; c++) { float t = xr[c] - m; v += t * t; }
        v += __shfl_xor_sync(0xffffffffu, v, 1);
        v += __shfl_xor_sync(0xffffffffu, v, 2);
        float rinv = rsqrtf(v * (1.f / 64.f) + 1e-5f);
#pragma unroll
        for (int c = 0; c < 16; c++) {
            int d2 = q4 * 16 + c;
            xr[c] = tf32r((xr[c] - m) * rinv * g1[d2] + be1[d2]);
        }
    }
    __syncthreads();

    int w = tid >> 5, lane = tid & 31;
    int g = lane >> 2, t = lane & 3;
    int mt = (w >> 1) * 16;
    int half = (w & 1);
    int nh = half * 32;

    float acc[4][4];   // term1 head-sum, persistent
#pragma unroll
    for (int nn = 0; nn < 4; nn++)
#pragma unroll
        for (int e2 = 0; e2 < 4; e2++) acc[nn][e2] = 0.f;

    for (int h = 0; h < 4; h++) {
        int wbase = (h * 2 + half) * 1024 + lane;
        // ---- phase A1: q projection + qe partials (16 accumulators live) ----
        {
            float dq[4][4];
#pragma unroll
            for (int nn = 0; nn < 4; nn++)
#pragma unroll
                for (int e2 = 0; e2 < 4; e2++) dq[nn][e2] = 0.f;
            for (int kk8 = 0; kk8 < 8; kk8++) {
                int kk = kk8 * 8;
                unsigned a0 = __float_as_uint(xn[(mt + g) * PAD + kk + t]);
                unsigned a1 = __float_as_uint(xn[(mt + g + 8) * PAD + kk + t]);
                unsigned a2 = __float_as_uint(xn[(mt + g) * PAD + kk + t + 4]);
                unsigned a3 = __float_as_uint(xn[(mt + g + 8) * PAD + kk + t + 4]);
                int fb = wbase + kk8 * 128;
#pragma unroll
                for (int nn = 0; nn < 4; nn++) {
                    float2 bq2 = g_Wq2[fb + nn * 32];
                    mma_tf32(dq[nn][0], dq[nn][1], dq[nn][2], dq[nn][3], a0, a1, a2, a3,
                             __float_as_uint(bq2.x), __float_as_uint(bq2.y));
                }
            }
            float pe0 = 0.f, pe8 = 0.f;
#pragma unroll
            for (int nn = 0; nn < 4; nn++) {
                int col = nh + nn * 8 + 2 * t;
                float bq0 = bq[h * 64 + col], bq1 = bq[h * 64 + col + 1];
                float we0 = We[h * 64 + col], we1 = We[h * 64 + col + 1];
                float q00 = dq[nn][0] + bq0, q01 = dq[nn][1] + bq1;
                float q80 = dq[nn][2] + bq0, q81 = dq[nn][3] + bq1;
                pe0 += q00 * we0 + q01 * we1;
                pe8 += q80 * we0 + q81 * we1;
                float2 p;
                p.x = tf32r(q00); p.y = tf32r(q01);
                *(float2*)&qb[(mt + g) * PAD + col] = p;
                p.x = tf32r(q80); p.y = tf32r(q81);
                *(float2*)&qb[(mt + g + 8) * PAD + col] = p;
            }
            pe0 += __shfl_xor_sync(0xffffffffu, pe0, 1);
            pe0 += __shfl_xor_sync(0xffffffffu, pe0, 2);
            pe8 += __shfl_xor_sync(0xffffffffu, pe8, 1);
            pe8 += __shfl_xor_sync(0xffffffffu, pe8, 2);
            if (t == 0) {
                auxp[half * 64 + mt + g] = pe0;
                auxp[half * 64 + mt + g + 8] = pe8;
            }
        }
        // ---- phase A2: k projection (separate pass to cap live regs) ----
        {
            float dk[4][4];
#pragma unroll
            for (int nn = 0; nn < 4; nn++)
#pragma unroll
                for (int e2 = 0; e2 < 4; e2++) dk[nn][e2] = 0.f;
            for (int kk8 = 0; kk8 < 8; kk8++) {
                int kk = kk8 * 8;
                unsigned a0 = __float_as_uint(xn[(mt + g) * PAD + kk + t]);
                unsigned a1 = __float_as_uint(xn[(mt + g + 8) * PAD + kk + t]);
                unsigned a2 = __float_as_uint(xn[(mt + g) * PAD + kk + t + 4]);
                unsigned a3 = __float_as_uint(xn[(mt + g + 8) * PAD + kk + t + 4]);
                int fb = wbase + kk8 * 128;
#pragma unroll
                for (int nn = 0; nn < 4; nn++) {
                    float2 bk2 = g_Wk2[fb + nn * 32];
                    mma_tf32(dk[nn][0], dk[nn][1], dk[nn][2], dk[nn][3], a0, a1, a2, a3,
                             __float_as_uint(bk2.x), __float_as_uint(bk2.y));
                }
            }
#pragma unroll
            for (int nn = 0; nn < 4; nn++) {
                int col = nh + nn * 8 + 2 * t;
                float bk0 = bk[h * 64 + col], bk1 = bk[h * 64 + col + 1];
                float2 p;
                p.x = tf32r(dk[nn][0] + bk0); p.y = tf32r(dk[nn][1] + bk1);
                *(float2*)&kb[(mt + g) * PAD + col] = p;
                p.x = tf32r(dk[nn][2] + bk0); p.y = tf32r(dk[nn][3] + bk1);
                *(float2*)&kb[(mt + g + 8) * PAD + col] = p;
            }
        }
        __syncthreads();
        // ---- phase B: scores = Q @ K^T; epilogue qe*w + mask ----
        {
            float ds[4][4];
#pragma unroll
            for (int nn = 0; nn < 4; nn++)
#pragma unroll
                for (int e2 = 0; e2 < 4; e2++) ds[nn][e2] = 0.f;
            for (int kk = 0; kk < 64; kk += 8) {
                unsigned a0 = __float_as_uint(qb[(mt + g) * PAD + kk + t]);
                unsigned a1 = __float_as_uint(qb[(mt + g + 8) * PAD + kk + t]);
                unsigned a2 = __float_as_uint(qb[(mt + g) * PAD + kk + t + 4]);
                unsigned a3 = __float_as_uint(qb[(mt + g + 8) * PAD + kk + t + 4]);
#pragma unroll
                for (int nn = 0; nn < 4; nn++) {
                    int n = nh + nn * 8 + g;
                    unsigned b0 = __float_as_uint(kb[n * PAD + kk + t]);
                    unsigned b1 = __float_as_uint(kb[n * PAD + kk + t + 4]);
                    mma_tf32(ds[nn][0], ds[nn][1], ds[nn][2], ds[nn][3], a0, a1, a2, a3, b0, b1);
                }
            }
            int i0 = mt + g, i8 = mt + g + 8;
            float qe0 = auxp[i0] + auxp[64 + i0];
            float qe8 = auxp[i8] + auxp[64 + i8];
#pragma unroll
            for (int nn = 0; nn < 4; nn++) {
                int j0 = nh + nn * 8 + 2 * t;
                float2 w0 = *(const float2*)&gw[i0 * 64 + j0];
                float2 w8 = *(const float2*)&gw[i8 * 64 + j0];
                float s00 = (ds[nn][0] + qe0 * w0.x) * 0.125f;
                float s01 = (ds[nn][1] + qe0 * w0.y) * 0.125f;
                float s80 = (ds[nn][2] + qe8 * w8.x) * 0.125f;
                float s81 = (ds[nn][3] + qe8 * w8.y) * 0.125f;
                attb[i0 * PAD + j0]     = (w0.x != 0.f) ? s00 : -1e30f;
                attb[i0 * PAD + j0 + 1] = (w0.y != 0.f) ? s01 : -1e30f;
                attb[i8 * PAD + j0]     = (w8.x != 0.f) ? s80 : -1e30f;
                attb[i8 * PAD + j0 + 1] = (w8.y != 0.f) ? s81 : -1e30f;
            }
        }
        __syncthreads();
        // ---- phase C1: softmax + coef (quad) ----
        {
            float* arow = &attb[r4 * PAD + q4 * 16];
            float e[16];
            float mx = -3e38f;
#pragma unroll
            for (int c = 0; c < 16; c++) { e[c] = arow[c]; mx = fmaxf(mx, e[c]); }
            mx = fmaxf(mx, __shfl_xor_sync(0xffffffffu, mx, 1));
            mx = fmaxf(mx, __shfl_xor_sync(0xffffffffu, mx, 2));
            float s = 0.f;
#pragma unroll
            for (int c = 0; c < 16; c++) { e[c] = expf(e[c] - mx); s += e[c]; }
            s += __shfl_xor_sync(0xffffffffu, s, 1);
            s += __shfl_xor_sync(0xffffffffu, s, 2);
            float inv = 1.f / s;
            const float4* wv4 = (const float4*)&gw[r4 * 64 + q4 * 16];
            float cf = 0.f;
#pragma unroll
            for (int c4 = 0; c4 < 4; c4++) {
                float4 wp = wv4[c4];
                float a0 = e[c4 * 4 + 0] * inv;
                float a1 = e[c4 * 4 + 1] * inv;
                float a2 = e[c4 * 4 + 2] * inv;
                float a3 = e[c4 * 4 + 3] * inv;
                cf += a0 * wp.x + a1 * wp.y + a2 * wp.z + a3 * wp.w;
                arow[c4 * 4 + 0] = tf32r(a0);
                arow[c4 * 4 + 1] = tf32r(a1);
                arow[c4 * 4 + 2] = tf32r(a2);
                arow[c4 * 4 + 3] = tf32r(a3);
            }
            cf += __shfl_xor_sync(0xffffffffu, cf, 1);
            cf += __shfl_xor_sync(0xffffffffu, cf, 2);
            if (q4 == 0) aux[r4] = cf;
        }
        // ---- phase C2: v projection -> vtb (alias of qb; qb dead after B) ----
        {
            float dv[4][4];
#pragma unroll
            for (int nn = 0; nn < 4; nn++)
#pragma unroll
                for (int e2 = 0; e2 < 4; e2++) dv[nn][e2] = 0.f;
            for (int kk8 = 0; kk8 < 8; kk8++) {
                int kk = kk8 * 8;
                unsigned a0 = __float_as_uint(xn[(mt + g) * PAD + kk + t]);
                unsigned a1 = __float_as_uint(xn[(mt + g + 8) * PAD + kk + t]);
                unsigned a2 = __float_as_uint(xn[(mt + g) * PAD + kk + t + 4]);
                unsigned a3 = __float_as_uint(xn[(mt + g + 8) * PAD + kk + t + 4]);
                int fb = wbase + kk8 * 128;
#pragma unroll
                for (int nn = 0; nn < 4; nn++) {
                    float2 bv2 = g_Wv2[fb + nn * 32];
                    mma_tf32(dv[nn][0], dv[nn][1], dv[nn][2], dv[nn][3], a0, a1, a2, a3,
                             __float_as_uint(bv2.x), __float_as_uint(bv2.y));
                }
            }
#pragma unroll
            for (int nn = 0; nn < 4; nn++) {
                int col = nh + nn * 8 + 2 * t;
                float bv0 = bv[h * 64 + col], bv1 = bv[h * 64 + col + 1];
                vtb[(col    ) * PAD + mt + g    ] = tf32r(dv[nn][0] + bv0);
                vtb[(col + 1) * PAD + mt + g    ] = tf32r(dv[nn][1] + bv1);
                vtb[(col    ) * PAD + mt + g + 8] = tf32r(dv[nn][2] + bv0);
                vtb[(col + 1) * PAD + mt + g + 8] = tf32r(dv[nn][3] + bv1);
            }
        }
        __syncthreads();
        // ---- phase D: term1 = Attn @ V into persistent acc; + coef*We ----
        {
            for (int kk = 0; kk < 64; kk += 8) {
                unsigned a0 = __float_as_uint(attb[(mt + g) * PAD + kk + t]);
                unsigned a1 = __float_as_uint(attb[(mt + g + 8) * PAD + kk + t]);
                unsigned a2 = __float_as_uint(attb[(mt + g) * PAD + kk + t + 4]);
                unsigned a3 = __float_as_uint(attb[(mt + g + 8) * PAD + kk + t + 4]);
#pragma unroll
                for (int nn = 0; nn < 4; nn++) {
                    int n = nh + nn * 8 + g;
                    unsigned b0 = __float_as_uint(vtb[n * PAD + kk + t]);
                    unsigned b1 = __float_as_uint(vtb[n * PAD + kk + t + 4]);
                    mma_tf32(acc[nn][0], acc[nn][1], acc[nn][2], acc[nn][3], a0, a1, a2, a3, b0, b1);
                }
            }
            float c0 = aux[mt + g], c8 = aux[mt + g + 8];
#pragma unroll
            for (int nn = 0; nn < 4; nn++) {
                int d0 = nh + nn * 8 + 2 * t;
                float we0 = We[h * 64 + d0], we1 = We[h * 64 + d0 + 1];
                acc[nn][0] += c0 * we0;
                acc[nn][1] += c0 * we1;
                acc[nn][2] += c8 * we0;
                acc[nn][3] += c8 * we1;
            }
        }
        __syncthreads();   // required: next head's A writes qb (= vtb read in D)
    }

    // ---- skip GEMM + combine -> attb ----
    {
        float sk[4][4];
#pragma unroll
        for (int nn = 0; nn < 4; nn++)
#pragma unroll
            for (int e2 = 0; e2 < 4; e2++) sk[nn][e2] = 0.f;
        for (int kk8 = 0; kk8 < 8; kk8++) {
            int kk = kk8 * 8;
            unsigned a0 = __float_as_uint(xn[(mt + g) * PAD + kk + t]);
            unsigned a1 = __float_as_uint(xn[(mt + g + 8) * PAD + kk + t]);
            unsigned a2 = __float_as_uint(xn[(mt + g) * PAD + kk + t + 4]);
            unsigned a3 = __float_as_uint(xn[(mt + g + 8) * PAD + kk + t + 4]);
            int fb = (half * 8 + kk8) * 128 + lane;
#pragma unroll
            for (int nn = 0; nn < 4; nn++) {
                float2 bs2 = g_Ws2[fb + nn * 32];
                mma_tf32(sk[nn][0], sk[nn][1], sk[nn][2], sk[nn][3], a0, a1, a2, a3,
                         __float_as_uint(bs2.x), __float_as_uint(bs2.y));
            }
        }
#pragma unroll
        for (int nn = 0; nn < 4; nn++) {
            int col = nh + nn * 8 + 2 * t;
            float2 p;
            p.x = 0.25f * acc[nn][0] + sk[nn][0];
            p.y = 0.25f * acc[nn][1] + sk[nn][1];
            *(float2*)&attb[(mt + g) * PAD + col] = p;
            p.x = 0.25f * acc[nn][2] + sk[nn][2];
            p.y = 0.25f * acc[nn][3] + sk[nn][3];
            *(float2*)&attb[(mt + g + 8) * PAD + col] = p;
        }
    }
    __syncthreads();

    // ---- residual + final LN over 4096 ----
    float part = 0.f;
    for (int e = tid; e < 4096; e += 256) {
        int i = e >> 6, dd = e & 63;
        float r = nf[e] + attb[i * PAD + dd] + bskip[dd];
        attb[i * PAD + dd] = r;
        part += r;
    }
    red[tid] = part;
    __syncthreads();
    for (int off = 128; off > 0; off >>= 1) {
        if (tid < off) red[tid] += red[tid + off];
        __syncthreads();
    }
    float mean = red[0] * (1.f / 4096.f);
    __syncthreads();
    part = 0.f;
    for (int e = tid; e < 4096; e += 256) {
        float tt = attb[(e >> 6) * PAD + (e & 63)] - mean;
        part += tt * tt;
    }
    red[tid] = part;
    __syncthreads();
    for (int off = 128; off > 0; off >>= 1) {
        if (tid < off) red[tid] += red[tid + off];
        __syncthreads();
    }
    float rinv = rsqrtf(red[0] * (1.f / 4096.f) + 1e-5f);
    __syncthreads();

    float* ob = out + (size_t)bs * 4096;
    for (int e = tid; e < 4096; e += 256) {
        ob[e] = (attb[(e >> 6) * PAD + (e & 63)] - mean) * rinv * g2[e] + be2[e];
    }
}

// ---------------- launcher ----------------
extern "C" void kernel_launch(void* const* d_in, const int* in_sizes, int n_in,
                              void* d_out, int out_size) {
    const float* pooled      = (const float*)d_in[0];
    const float* node_feats  = (const float*)d_in[1];
    const float* pos         = (const float*)d_in[2];
    const float* Wpos        = (const float*)d_in[3];
    const float* W1          = (const float*)d_in[4];
    const float* b1          = (const float*)d_in[5];
    const float* W2          = (const float*)d_in[6];
    const float* b2          = (const float*)d_in[7];
    const float* log_tau     = (const float*)d_in[8];
    const float* logit_theta = (const float*)d_in[9];
    const float* logit_alpha = (const float*)d_in[10];
    const float* raw_beta    = (const float*)d_in[11];
    const float* Wq          = (const float*)d_in[12];
    const float* bq          = (const float*)d_in[13];
    const float* Wk          = (const float*)d_in[14];
    const float* bk          = (const float*)d_in[15];
    const float* Wv          = (const float*)d_in[16];
    const float* bv          = (const float*)d_in[17];
    const float* We          = (const float*)d_in[18];
    const float* Wskip       = (const float*)d_in[19];
    const float* bskip       = (const float*)d_in[20];
    const float* g1          = (const float*)d_in[21];
    const float* be1         = (const float*)d_in[22];
    const float* g2          = (const float*)d_in[23];
    const float* be2         = (const float*)d_in[24];
    float* out = (float*)d_out;

    const int adj_smem  = (64 * 33 + 64 + 64 + 3 * 64 * 65) * 4;
    const int attn_smem = (4 * 64 * PAD + 128 + 64 + 256) * 4;   // 71,424 B
    cudaFuncSetAttribute(k_adj,  cudaFuncAttributeMaxDynamicSharedMemorySize, adj_smem);
    cudaFuncSetAttribute(k_attn, cudaFuncAttributeMaxDynamicSharedMemorySize, attn_smem);

    k_init<<<1024, 256>>>(b1, b2);
    k_packT<<<32, 256>>>(Wq, Wk, Wv, Wskip);
    k_setup<<<1, 64>>>(pos, Wpos);
    k_mlp1<<<dim3(32, 64), 256>>>(pooled, W1);
    k_mlp2<<<dim3(8, 128), 256>>>(W2);
    k_adj<<<32, 256, adj_smem>>>(log_tau, logit_theta, logit_alpha, raw_beta);
    k_attn<<<4096, 256, attn_smem>>>(node_feats, bq, bk, bv, We, bskip,
                                     g1, be1, g2, be2, out);
}